// round 5
// baseline (speedup 1.0000x reference)
#include <cuda_runtime.h>
#include <math.h>
#include <stdint.h>

#define D      128
#define TILE   256
#define NTHR   512
#define MAXN   51200
#define AST    132          // A smem row stride in floats (conflict-free frag loads)

// ---------------------------------------------------------------------------
// Static device scratch (no cudaMalloc allowed)
// ---------------------------------------------------------------------------
__device__ float    g_agg[(size_t)MAXN * D];     // scatter-add target
__device__ uint32_t g_Bfrag[4][16384];           // tf32 W images in mma-fragment order
// 0 = We1, 1 = We2, 2 = Wu1, 3 = Wu2

__device__ __forceinline__ uint32_t f2tf(float f) {
    uint32_t r;
    asm("cvt.rna.tf32.f32 %0, %1;" : "=r"(r) : "f"(f));
    return r;
}

__device__ __forceinline__ uint32_t smem_u32(const void* p) {
    uint32_t a;
    asm("{ .reg .u64 t; cvta.to.shared.u64 t, %1; cvt.u32.u64 %0, t; }" : "=r"(a) : "l"(p));
    return a;
}

__device__ __forceinline__ void cp_async16(uint32_t s, const void* g) {
    asm volatile("cp.async.cg.shared.global [%0], [%1], 16;" :: "r"(s), "l"(g));
}
#define CP_COMMIT() asm volatile("cp.async.commit_group;" ::: "memory")
#define CP_WAIT0()  asm volatile("cp.async.wait_group 0;" ::: "memory")

__device__ __forceinline__ float gelu_exact(float v) {
    return 0.5f * v * (1.0f + erff(v * 0.70710678118654752f));
}

__device__ __forceinline__ void mma_tf32(float* c,
                                         uint32_t a0, uint32_t a1, uint32_t a2, uint32_t a3,
                                         uint32_t b0, uint32_t b1) {
    asm volatile(
        "mma.sync.aligned.m16n8k8.row.col.f32.tf32.tf32.f32 "
        "{%0,%1,%2,%3}, {%4,%5,%6,%7}, {%8,%9}, {%0,%1,%2,%3};"
        : "+f"(c[0]), "+f"(c[1]), "+f"(c[2]), "+f"(c[3])
        : "r"(a0), "r"(a1), "r"(a2), "r"(a3), "r"(b0), "r"(b1));
}

__device__ __forceinline__ void red_add_v4(float* p, float4 v) {
    asm volatile("red.global.add.v4.f32 [%0], {%1,%2,%3,%4};"
                 :: "l"(p), "f"(v.x), "f"(v.y), "f"(v.z), "f"(v.w) : "memory");
}

// ---------------------------------------------------------------------------
// Weight prep: W[k][n] -> tf32 bits in m16n8k8 B-fragment order.
//   idx = (catom*16 + kstep)*64 + lane*2 + slot
//   catom = n>>3, kstep = k>>3, lane = ((n&7)<<2)|(k&3), slot = (k>>2)&1
// ---------------------------------------------------------------------------
__global__ void prep_weights(const float* __restrict__ We1, const float* __restrict__ We2,
                             const float* __restrict__ Wu1, const float* __restrict__ Wu2)
{
    int id = blockIdx.x * blockDim.x + threadIdx.x;
    if (id >= 4 * 16384) return;
    int m = id >> 14, r = id & 16383, k = r >> 7, n = r & 127;
    const float* W = (m == 0) ? We1 : (m == 1) ? We2 : (m == 2) ? Wu1 : Wu2;
    float v = W[k * D + n];
    int c = n >> 3, s = k >> 3, lane = ((n & 7) << 2) | (k & 3), slot = (k >> 2) & 1;
    g_Bfrag[m][(c * 16 + s) * 64 + lane * 2 + slot] = f2tf(v);
}

// ---------------------------------------------------------------------------
// One 128-col GEMM pass on the staged A tile. Warp computes 32 rows x 64 cols.
// ---------------------------------------------------------------------------
__device__ __forceinline__ void do_gemm(const float* __restrict__ Abase,
                                        const uint32_t* __restrict__ Bw,
                                        float acc[2][8][4])
{
    #pragma unroll
    for (int ma = 0; ma < 2; ++ma)
        #pragma unroll
        for (int ca = 0; ca < 8; ++ca)
            #pragma unroll
            for (int q = 0; q < 4; ++q) acc[ma][ca][q] = 0.f;

    #pragma unroll
    for (int s = 0; s < 16; ++s) {
        uint32_t a[2][4];
        #pragma unroll
        for (int ma = 0; ma < 2; ++ma) {
            const float* q = Abase + ma * (16 * AST) + s * 8;
            a[ma][0] = __float_as_uint(q[0]);
            a[ma][1] = __float_as_uint(q[8 * AST]);
            a[ma][2] = __float_as_uint(q[4]);
            a[ma][3] = __float_as_uint(q[8 * AST + 4]);
        }
        const uint2* bp = (const uint2*)(Bw + s * 64);
        #pragma unroll
        for (int ca = 0; ca < 8; ++ca) {
            uint2 b = bp[ca * 512];       // catom stride = 1024 uints = 512 uint2
            mma_tf32(acc[0][ca], a[0][0], a[0][1], a[0][2], a[0][3], b.x, b.y);
            mma_tf32(acc[1][ca], a[1][0], a[1][1], a[1][2], a[1][3], b.x, b.y);
        }
    }
}

// ---------------------------------------------------------------------------
// Fused 2-layer MLP on a 256-row tile. 16 warps: 8 row-groups x 2 col-groups.
// Single B buffer; B2 prefetch (cp.async) overlaps the GELU epilogue.
// EDGE: A = x[src]+ea -> MLP -> red.v4 scatter into g_agg[dst]
// NODE: A = (1+eps)*x + g_agg -> MLP -> out
// ---------------------------------------------------------------------------
template <bool EDGE>
__global__ void __launch_bounds__(NTHR, 1) fused_mlp_mma(
    const float* __restrict__ x,
    const int*   __restrict__ src,
    const int*   __restrict__ dst,
    const float* __restrict__ ea,
    const float* __restrict__ b1,
    const float* __restrict__ b2,
    const float* __restrict__ eps,
    float*       __restrict__ out,
    int count)
{
    extern __shared__ float smem[];
    float*    As = smem;                               // [256][AST]
    uint32_t* Bs = (uint32_t*)(smem + TILE * AST);     // one 64KB B fragment image
    const uint32_t Bs_u32 = smem_u32(Bs);

    const int tid  = threadIdx.x;
    const int lane = tid & 31, wid = tid >> 5;
    const int wm = wid & 7, wn = wid >> 3;             // 8 row-groups x 2 col-groups
    const int g = lane >> 2, t = lane & 3;
    const int r0 = blockIdx.x * TILE;
    const int imgbase = EDGE ? 0 : 2;

    // ---- prefetch B1 (64KB) via cp.async, overlapped with A gather ----
    {
        const uint4* gsrc = (const uint4*)(&g_Bfrag[imgbase][0]);
        #pragma unroll
        for (int i = 0; i < 8; ++i) {
            int idx = i * NTHR + tid;
            cp_async16(Bs_u32 + idx * 16, gsrc + idx);
        }
        CP_COMMIT();
    }

    // ---- stage A (tf32 bits): each thread handles one row-half ----
    {
        int r = tid >> 1;
        int half = (tid & 1) * 64;
        int row = r0 + r;
        float* drow = As + r * AST + half;
        if (row < count) {
            const float4* xr;
            const float4* er;
            float oe = 0.f;
            if (EDGE) {
                int sidx = src[row];
                xr = (const float4*)(x + (size_t)sidx * D + half);
                er = (const float4*)(ea + (size_t)row * D + half);
            } else {
                oe = 1.0f + eps[0];
                xr = (const float4*)(x + (size_t)row * D + half);
                er = (const float4*)(g_agg + (size_t)row * D + half);
            }
            #pragma unroll
            for (int i = 0; i < 16; ++i) {
                float4 a = xr[i], b = er[i];
                float f0, f1, f2, f3;
                if (EDGE) { f0 = a.x + b.x; f1 = a.y + b.y; f2 = a.z + b.z; f3 = a.w + b.w; }
                else { f0 = fmaf(oe, a.x, b.x); f1 = fmaf(oe, a.y, b.y);
                       f2 = fmaf(oe, a.z, b.z); f3 = fmaf(oe, a.w, b.w); }
                uint4 u = make_uint4(f2tf(f0), f2tf(f1), f2tf(f2), f2tf(f3));
                *(uint4*)(drow + i * 4) = u;
            }
        } else {
            #pragma unroll
            for (int i = 0; i < 16; ++i)
                *(uint4*)(drow + i * 4) = make_uint4(0u, 0u, 0u, 0u);
        }
    }
    CP_WAIT0();
    __syncthreads();

    const float* Abase = As + (wm * 32 + g) * AST + t;
    const uint32_t* Bw = Bs + wn * 8192 + lane * 2;    // wn*8 catoms * 1024 uints

    float acc[2][8][4];

    // ---- GEMM1 ----
    do_gemm(Abase, Bw, acc);
    __syncthreads();     // A + B1 reads complete

    // ---- prefetch B2, overlapped with GELU epilogue ----
    {
        const uint4* gsrc = (const uint4*)(&g_Bfrag[imgbase + 1][0]);
        #pragma unroll
        for (int i = 0; i < 8; ++i) {
            int idx = i * NTHR + tid;
            cp_async16(Bs_u32 + idx * 16, gsrc + idx);
        }
        CP_COMMIT();
    }

    // ---- epilogue1: H = GELU(C + b1) -> As (tf32 bits) ----
    #pragma unroll
    for (int ca = 0; ca < 8; ++ca) {
        int col = wn * 64 + ca * 8 + 2 * t;
        float bb0 = __ldg(&b1[col]), bb1 = __ldg(&b1[col + 1]);
        #pragma unroll
        for (int ma = 0; ma < 2; ++ma) {
            int row = wm * 32 + ma * 16 + g;
            float h0 = gelu_exact(acc[ma][ca][0] + bb0);
            float h1 = gelu_exact(acc[ma][ca][1] + bb1);
            float h2 = gelu_exact(acc[ma][ca][2] + bb0);
            float h3 = gelu_exact(acc[ma][ca][3] + bb1);
            *(uint2*)(As + row * AST + col)       = make_uint2(f2tf(h0), f2tf(h1));
            *(uint2*)(As + (row + 8) * AST + col) = make_uint2(f2tf(h2), f2tf(h3));
        }
    }
    CP_WAIT0();
    __syncthreads();

    // ---- GEMM2 ----
    do_gemm(Abase, Bw, acc);
    __syncthreads();     // H reads complete before C2 overwrite

    // ---- epilogue2: raw C2 -> As (fp32) ----
    #pragma unroll
    for (int ca = 0; ca < 8; ++ca) {
        int col = wn * 64 + ca * 8 + 2 * t;
        #pragma unroll
        for (int ma = 0; ma < 2; ++ma) {
            int row = wm * 32 + ma * 16 + g;
            *(float2*)(As + row * AST + col)       = make_float2(acc[ma][ca][0], acc[ma][ca][1]);
            *(float2*)(As + (row + 8) * AST + col) = make_float2(acc[ma][ca][2], acc[ma][ca][3]);
        }
    }
    __syncthreads();

    // ---- output: coalesced + bias; edge -> red.v4 scatter, node -> store ----
    {
        int c4 = lane * 4;
        float4 bias = *(const float4*)&b2[c4];
        int rbase = wid * 16;
        #pragma unroll
        for (int i = 0; i < 16; ++i) {
            int r = rbase + i;
            int row = r0 + r;
            if (row < count) {
                float4 v = *(float4*)(As + r * AST + c4);
                v.x += bias.x; v.y += bias.y; v.z += bias.z; v.w += bias.w;
                if (EDGE) {
                    int dn = dst[row];
                    red_add_v4(g_agg + (size_t)dn * D + c4, v);
                } else {
                    *(float4*)(out + (size_t)row * D + c4) = v;
                }
            }
        }
    }
}

// ---------------------------------------------------------------------------
// Inputs: x, edge_index(int32 [2,E]), edge_attr, We1, be1, We2, be2,
//         Wu1, bu1, Wu2, bu2, eps
// ---------------------------------------------------------------------------
extern "C" void kernel_launch(void* const* d_in, const int* in_sizes, int n_in,
                              void* d_out, int out_size)
{
    const float* x   = (const float*)d_in[0];
    const int*   ei  = (const int*)d_in[1];
    const float* ea  = (const float*)d_in[2];
    const float* We1 = (const float*)d_in[3];
    const float* be1 = (const float*)d_in[4];
    const float* We2 = (const float*)d_in[5];
    const float* be2 = (const float*)d_in[6];
    const float* Wu1 = (const float*)d_in[7];
    const float* bu1 = (const float*)d_in[8];
    const float* Wu2 = (const float*)d_in[9];
    const float* bu2 = (const float*)d_in[10];
    const float* eps = (const float*)d_in[11];
    float*       out = (float*)d_out;

    const int N = in_sizes[0] / D;
    const int E = in_sizes[1] / 2;
    const int* src = ei;
    const int* dst = ei + E;

    const int SMEM_BYTES = (TILE * AST + 16384) * 4;   // 200704
    cudaFuncSetAttribute(fused_mlp_mma<true>,  cudaFuncAttributeMaxDynamicSharedMemorySize, SMEM_BYTES);
    cudaFuncSetAttribute(fused_mlp_mma<false>, cudaFuncAttributeMaxDynamicSharedMemorySize, SMEM_BYTES);

    prep_weights<<<256, 256>>>(We1, We2, Wu1, Wu2);

    void* aggp = nullptr;
    cudaGetSymbolAddress(&aggp, g_agg);
    cudaMemsetAsync(aggp, 0, (size_t)N * D * sizeof(float), 0);

    int eblocks = (E + TILE - 1) / TILE;
    fused_mlp_mma<true><<<eblocks, NTHR, SMEM_BYTES>>>(x, src, dst, ea, be1, be2, eps, out, E);

    int nblocks = (N + TILE - 1) / TILE;
    fused_mlp_mma<false><<<nblocks, NTHR, SMEM_BYTES>>>(x, src, dst, ea, bu1, bu2, eps, out, N);
}

// round 6
// speedup vs baseline: 1.5270x; 1.5270x over previous
#include <cuda_runtime.h>
#include <math.h>
#include <stdint.h>

#define D      128
#define TILE   128
#define NTHR   256
#define MAXN   51200
#define AST    132          // A smem row stride in floats (conflict-free frag loads)

// ---------------------------------------------------------------------------
// Static device scratch (no cudaMalloc allowed)
// ---------------------------------------------------------------------------
__device__ float    g_agg[(size_t)MAXN * D];     // scatter-add target
__device__ uint32_t g_Bfrag[4][16384];           // tf32 W images in mma-fragment order
// 0 = We1, 1 = We2, 2 = Wu1, 3 = Wu2

__device__ __forceinline__ uint32_t f2tf(float f) {
    uint32_t r;
    asm("cvt.rna.tf32.f32 %0, %1;" : "=r"(r) : "f"(f));
    return r;
}

__device__ __forceinline__ float gelu_exact(float v) {
    return 0.5f * v * (1.0f + erff(v * 0.70710678118654752f));
}

__device__ __forceinline__ void mma_tf32(float* c,
                                         uint32_t a0, uint32_t a1, uint32_t a2, uint32_t a3,
                                         uint32_t b0, uint32_t b1) {
    asm volatile(
        "mma.sync.aligned.m16n8k8.row.col.f32.tf32.tf32.f32 "
        "{%0,%1,%2,%3}, {%4,%5,%6,%7}, {%8,%9}, {%0,%1,%2,%3};"
        : "+f"(c[0]), "+f"(c[1]), "+f"(c[2]), "+f"(c[3])
        : "r"(a0), "r"(a1), "r"(a2), "r"(a3), "r"(b0), "r"(b1));
}

__device__ __forceinline__ void red_add_v4(float* p, float4 v) {
    asm volatile("red.global.add.v4.f32 [%0], {%1,%2,%3,%4};"
                 :: "l"(p), "f"(v.x), "f"(v.y), "f"(v.z), "f"(v.w) : "memory");
}

// ---------------------------------------------------------------------------
// Weight prep: W[k][n] -> tf32 bits in m16n8k8 B-fragment order.
//   idx = (catom*16 + kstep)*64 + lane*2 + slot
//   catom = n>>3, kstep = k>>3, lane = ((n&7)<<2)|(k&3), slot = (k>>2)&1
// ---------------------------------------------------------------------------
__global__ void prep_weights(const float* __restrict__ We1, const float* __restrict__ We2,
                             const float* __restrict__ Wu1, const float* __restrict__ Wu2)
{
    int id = blockIdx.x * blockDim.x + threadIdx.x;
    if (id >= 4 * 16384) return;
    int m = id >> 14, r = id & 16383, k = r >> 7, n = r & 127;
    const float* W = (m == 0) ? We1 : (m == 1) ? We2 : (m == 2) ? Wu1 : Wu2;
    float v = W[k * D + n];
    int c = n >> 3, s = k >> 3, lane = ((n & 7) << 2) | (k & 3), slot = (k >> 2) & 1;
    g_Bfrag[m][(c * 16 + s) * 64 + lane * 2 + slot] = f2tf(v);
}

// ---------------------------------------------------------------------------
// 128x64x128 GEMM slice: A from smem (LDS), B fragments straight from global
// (L1-resident weight image). Warp computes 32 rows x 64 cols.
// Bwarp = image + wn*8192 + lane*2 (uint32 units).
// ---------------------------------------------------------------------------
__device__ __forceinline__ void do_gemm(const float* __restrict__ Abase,
                                        const uint32_t* __restrict__ Bwarp,
                                        float acc[2][8][4])
{
    #pragma unroll
    for (int ma = 0; ma < 2; ++ma)
        #pragma unroll
        for (int ca = 0; ca < 8; ++ca)
            #pragma unroll
            for (int q = 0; q < 4; ++q) acc[ma][ca][q] = 0.f;

    #pragma unroll
    for (int s = 0; s < 16; ++s) {
        uint32_t a[2][4];
        #pragma unroll
        for (int ma = 0; ma < 2; ++ma) {
            const float* q = Abase + ma * (16 * AST) + s * 8;
            a[ma][0] = __float_as_uint(q[0]);
            a[ma][1] = __float_as_uint(q[8 * AST]);
            a[ma][2] = __float_as_uint(q[4]);
            a[ma][3] = __float_as_uint(q[8 * AST + 4]);
        }
        #pragma unroll
        for (int ca = 0; ca < 8; ++ca) {
            uint2 b = __ldg((const uint2*)(Bwarp + (ca * 16 + s) * 64));
            mma_tf32(acc[0][ca], a[0][0], a[0][1], a[0][2], a[0][3], b.x, b.y);
            mma_tf32(acc[1][ca], a[1][0], a[1][1], a[1][2], a[1][3], b.x, b.y);
        }
    }
}

// ---------------------------------------------------------------------------
// Fused 2-layer MLP on a 128-row tile. 8 warps: 4 row-groups x 2 col-groups.
// smem holds ONLY the A/H/C tile -> 2 CTAs/SM.
// EDGE: A = x[src]+ea -> MLP -> red.v4 scatter into g_agg[dst]
// NODE: A = (1+eps)*x + g_agg -> MLP -> out
// ---------------------------------------------------------------------------
template <bool EDGE>
__global__ void __launch_bounds__(NTHR, 2) fused_mlp_mma(
    const float* __restrict__ x,
    const int*   __restrict__ src,
    const int*   __restrict__ dst,
    const float* __restrict__ ea,
    const float* __restrict__ b1,
    const float* __restrict__ b2,
    const float* __restrict__ eps,
    float*       __restrict__ out,
    int count)
{
    extern __shared__ float As[];                      // [128][AST]

    const int tid  = threadIdx.x;
    const int lane = tid & 31, wid = tid >> 5;
    const int wm = wid & 3, wn = wid >> 2;             // 4 row-groups x 2 col-groups
    const int g = lane >> 2, t = lane & 3;
    const int r0 = blockIdx.x * TILE;
    const int imgbase = EDGE ? 0 : 2;

    // ---- stage A (tf32 bits): each thread handles one row-half ----
    {
        int r = tid >> 1;
        int half = (tid & 1) * 64;
        int row = r0 + r;
        float* drow = As + r * AST + half;
        if (row < count) {
            const float4* xr;
            const float4* er;
            float oe = 0.f;
            if (EDGE) {
                int sidx = __ldg(&src[row]);
                xr = (const float4*)(x + (size_t)sidx * D + half);
                er = (const float4*)(ea + (size_t)row * D + half);
            } else {
                oe = 1.0f + eps[0];
                xr = (const float4*)(x + (size_t)row * D + half);
                er = (const float4*)(g_agg + (size_t)row * D + half);
            }
            #pragma unroll
            for (int i = 0; i < 16; ++i) {
                float4 a = __ldg(xr + i), b = __ldg(er + i);
                float f0, f1, f2, f3;
                if (EDGE) { f0 = a.x + b.x; f1 = a.y + b.y; f2 = a.z + b.z; f3 = a.w + b.w; }
                else { f0 = fmaf(oe, a.x, b.x); f1 = fmaf(oe, a.y, b.y);
                       f2 = fmaf(oe, a.z, b.z); f3 = fmaf(oe, a.w, b.w); }
                uint4 u = make_uint4(f2tf(f0), f2tf(f1), f2tf(f2), f2tf(f3));
                *(uint4*)(drow + i * 4) = u;
            }
        } else {
            #pragma unroll
            for (int i = 0; i < 16; ++i)
                *(uint4*)(drow + i * 4) = make_uint4(0u, 0u, 0u, 0u);
        }
    }
    __syncthreads();

    const float* Abase = As + (wm * 32 + g) * AST + t;
    const uint32_t* Bw1 = &g_Bfrag[imgbase][0]     + wn * 8192 + lane * 2;
    const uint32_t* Bw2 = &g_Bfrag[imgbase + 1][0] + wn * 8192 + lane * 2;

    float acc[2][8][4];

    // ---- GEMM1 (A smem, B1 from L1) ----
    do_gemm(Abase, Bw1, acc);
    __syncthreads();     // everyone done reading A before H overwrite

    // ---- epilogue1: H = GELU(C + b1) -> As (tf32 bits) ----
    #pragma unroll
    for (int ca = 0; ca < 8; ++ca) {
        int col = wn * 64 + ca * 8 + 2 * t;
        float bb0 = __ldg(&b1[col]), bb1 = __ldg(&b1[col + 1]);
        #pragma unroll
        for (int ma = 0; ma < 2; ++ma) {
            int row = wm * 32 + ma * 16 + g;
            float h0 = gelu_exact(acc[ma][ca][0] + bb0);
            float h1 = gelu_exact(acc[ma][ca][1] + bb1);
            float h2 = gelu_exact(acc[ma][ca][2] + bb0);
            float h3 = gelu_exact(acc[ma][ca][3] + bb1);
            *(uint2*)(As + row * AST + col)       = make_uint2(f2tf(h0), f2tf(h1));
            *(uint2*)(As + (row + 8) * AST + col) = make_uint2(f2tf(h2), f2tf(h3));
        }
    }
    __syncthreads();

    // ---- GEMM2 ----
    do_gemm(Abase, Bw2, acc);
    __syncthreads();     // H reads complete before C2 overwrite

    // ---- epilogue2: raw C2 -> As (fp32) ----
    #pragma unroll
    for (int ca = 0; ca < 8; ++ca) {
        int col = wn * 64 + ca * 8 + 2 * t;
        #pragma unroll
        for (int ma = 0; ma < 2; ++ma) {
            int row = wm * 32 + ma * 16 + g;
            *(float2*)(As + row * AST + col)       = make_float2(acc[ma][ca][0], acc[ma][ca][1]);
            *(float2*)(As + (row + 8) * AST + col) = make_float2(acc[ma][ca][2], acc[ma][ca][3]);
        }
    }
    __syncthreads();

    // ---- output: coalesced + bias; edge -> red.v4 scatter, node -> store ----
    {
        int c4 = lane * 4;
        float4 bias = *(const float4*)&b2[c4];
        int rbase = wid * 16;
        #pragma unroll
        for (int i = 0; i < 16; ++i) {
            int r = rbase + i;
            int row = r0 + r;
            if (row < count) {
                float4 v = *(float4*)(As + r * AST + c4);
                v.x += bias.x; v.y += bias.y; v.z += bias.z; v.w += bias.w;
                if (EDGE) {
                    int dn = __ldg(&dst[row]);
                    red_add_v4(g_agg + (size_t)dn * D + c4, v);
                } else {
                    *(float4*)(out + (size_t)row * D + c4) = v;
                }
            }
        }
    }
}

// ---------------------------------------------------------------------------
// Inputs: x, edge_index(int32 [2,E]), edge_attr, We1, be1, We2, be2,
//         Wu1, bu1, Wu2, bu2, eps
// ---------------------------------------------------------------------------
extern "C" void kernel_launch(void* const* d_in, const int* in_sizes, int n_in,
                              void* d_out, int out_size)
{
    const float* x   = (const float*)d_in[0];
    const int*   ei  = (const int*)d_in[1];
    const float* ea  = (const float*)d_in[2];
    const float* We1 = (const float*)d_in[3];
    const float* be1 = (const float*)d_in[4];
    const float* We2 = (const float*)d_in[5];
    const float* be2 = (const float*)d_in[6];
    const float* Wu1 = (const float*)d_in[7];
    const float* bu1 = (const float*)d_in[8];
    const float* Wu2 = (const float*)d_in[9];
    const float* bu2 = (const float*)d_in[10];
    const float* eps = (const float*)d_in[11];
    float*       out = (float*)d_out;

    const int N = in_sizes[0] / D;
    const int E = in_sizes[1] / 2;
    const int* src = ei;
    const int* dst = ei + E;

    const int SMEM_BYTES = TILE * AST * 4;   // 67584 — A tile only => 2 CTAs/SM
    cudaFuncSetAttribute(fused_mlp_mma<true>,  cudaFuncAttributeMaxDynamicSharedMemorySize, SMEM_BYTES);
    cudaFuncSetAttribute(fused_mlp_mma<false>, cudaFuncAttributeMaxDynamicSharedMemorySize, SMEM_BYTES);

    prep_weights<<<256, 256>>>(We1, We2, Wu1, Wu2);

    void* aggp = nullptr;
    cudaGetSymbolAddress(&aggp, g_agg);
    cudaMemsetAsync(aggp, 0, (size_t)N * D * sizeof(float), 0);

    int eblocks = (E + TILE - 1) / TILE;
    fused_mlp_mma<true><<<eblocks, NTHR, SMEM_BYTES>>>(x, src, dst, ea, be1, be2, eps, out, E);

    int nblocks = (N + TILE - 1) / TILE;
    fused_mlp_mma<false><<<nblocks, NTHR, SMEM_BYTES>>>(x, src, dst, ea, bu1, bu2, eps, out, N);
}

// round 7
// speedup vs baseline: 1.8477x; 1.2100x over previous
#include <cuda_runtime.h>
#include <math.h>
#include <stdint.h>

#define D      128
#define TILE   128
#define NTHR   256
#define MAXN   51200

// ---------------------------------------------------------------------------
// Static device scratch (no cudaMalloc allowed)
// ---------------------------------------------------------------------------
__device__ float    g_agg[(size_t)MAXN * D];     // scatter-add target
__device__ uint32_t g_Bfrag[4][16384];           // tf32 W images, uint4-packed frag order
// 0 = We1, 1 = We2, 2 = Wu1, 3 = Wu2

__device__ __forceinline__ uint32_t f2tf(float f) {
    uint32_t r;
    asm("cvt.rna.tf32.f32 %0, %1;" : "=r"(r) : "f"(f));
    return r;
}

__device__ __forceinline__ float gelu_exact(float v) {
    return 0.5f * v * (1.0f + erff(v * 0.70710678118654752f));
}

__device__ __forceinline__ void mma_tf32(float* c,
                                         uint32_t a0, uint32_t a1, uint32_t a2, uint32_t a3,
                                         uint32_t b0, uint32_t b1) {
    asm volatile(
        "mma.sync.aligned.m16n8k8.row.col.f32.tf32.tf32.f32 "
        "{%0,%1,%2,%3}, {%4,%5,%6,%7}, {%8,%9}, {%0,%1,%2,%3};"
        : "+f"(c[0]), "+f"(c[1]), "+f"(c[2]), "+f"(c[3])
        : "r"(a0), "r"(a1), "r"(a2), "r"(a3), "r"(b0), "r"(b1));
}

__device__ __forceinline__ void red_add_v4(float* p, float4 v) {
    asm volatile("red.global.add.v4.f32 [%0], {%1,%2,%3,%4};"
                 :: "l"(p), "f"(v.x), "f"(v.y), "f"(v.z), "f"(v.w) : "memory");
}

// ---------------------------------------------------------------------------
// prep: (a) W[k][n] -> tf32 bits, uint4-packed fragment order:
//   idx32 = ((ca*8 + (s>>1))*32 + lane)*4 + (s&1)*2 + slot
//   ca = n>>3, s = k>>3, lane = ((n&7)<<2)|(k&3), slot = (k>>2)&1
// (b) zero g_agg (grid-stride), replacing the separate memset launch.
// ---------------------------------------------------------------------------
__global__ void prep_weights(const float* __restrict__ We1, const float* __restrict__ We2,
                             const float* __restrict__ Wu1, const float* __restrict__ Wu2,
                             size_t nd)
{
    int id = blockIdx.x * blockDim.x + threadIdx.x;
    if (id < 4 * 16384) {
        int m = id >> 14, r = id & 16383, k = r >> 7, n = r & 127;
        const float* W = (m == 0) ? We1 : (m == 1) ? We2 : (m == 2) ? Wu1 : Wu2;
        float v = W[k * D + n];
        int ca = n >> 3, s = k >> 3, lane = ((n & 7) << 2) | (k & 3), slot = (k >> 2) & 1;
        int idx = ((ca * 8 + (s >> 1)) * 32 + lane) * 4 + (s & 1) * 2 + slot;
        g_Bfrag[m][idx] = f2tf(v);
    }
    size_t stride = (size_t)gridDim.x * blockDim.x * 4;
    float4 z = make_float4(0.f, 0.f, 0.f, 0.f);
    for (size_t i = (size_t)id * 4; i < nd; i += stride)
        *(float4*)(g_agg + i) = z;
}

// ---------------------------------------------------------------------------
// 128x64x128 GEMM slice; A fragment-major in smem (LDS.128), B uint4 frags
// straight from the L1-resident global image (LDG.128).
// Bq = image_u4 + wn*2048 + lane.
// ---------------------------------------------------------------------------
__device__ __forceinline__ void do_gemm(const uint4* __restrict__ As4,
                                        const uint4* __restrict__ Bq,
                                        int ra0, int lane,
                                        float acc[2][8][4])
{
    #pragma unroll
    for (int ma = 0; ma < 2; ++ma)
        #pragma unroll
        for (int ca = 0; ca < 8; ++ca)
            #pragma unroll
            for (int q = 0; q < 4; ++q) acc[ma][ca][q] = 0.f;

    const int ra1 = ra0 + 1;
    #pragma unroll
    for (int sp = 0; sp < 8; ++sp) {
        int s0 = sp * 2, s1 = s0 + 1;
        uint4 aA0 = As4[(ra0 * 16 + s0) * 33 + lane];
        uint4 aA1 = As4[(ra0 * 16 + s1) * 33 + lane];
        uint4 aB0 = As4[(ra1 * 16 + s0) * 33 + lane];
        uint4 aB1 = As4[(ra1 * 16 + s1) * 33 + lane];
        #pragma unroll
        for (int ca = 0; ca < 8; ++ca) {
            uint4 b = __ldg(Bq + (ca * 8 + sp) * 32);
            mma_tf32(acc[0][ca], aA0.x, aA0.y, aA0.z, aA0.w, b.x, b.y);
            mma_tf32(acc[0][ca], aA1.x, aA1.y, aA1.z, aA1.w, b.z, b.w);
            mma_tf32(acc[1][ca], aB0.x, aB0.y, aB0.z, aB0.w, b.x, b.y);
            mma_tf32(acc[1][ca], aB1.x, aB1.y, aB1.z, aB1.w, b.z, b.w);
        }
    }
}

// ---------------------------------------------------------------------------
// Fused 2-layer MLP on a 128-row tile. 8 warps: 4 row-groups x 2 col-groups.
// smem = one 67.6KB fragment/linear tile buffer -> 2 CTAs/SM.
// ---------------------------------------------------------------------------
template <bool EDGE>
__global__ void __launch_bounds__(NTHR, 2) fused_mlp_mma(
    const float* __restrict__ x,
    const int*   __restrict__ src,
    const int*   __restrict__ dst,
    const float* __restrict__ ea,
    const float* __restrict__ b1,
    const float* __restrict__ b2,
    const float* __restrict__ eps,
    float*       __restrict__ out,
    int count)
{
    extern __shared__ float Asf[];                 // 16896 floats = 4224 uint4
    uint4* As4 = (uint4*)Asf;

    const int tid  = threadIdx.x;
    const int lane = tid & 31, wid = tid >> 5;
    const int wm = wid & 3, wn = wid >> 2;         // 4 row-groups x 2 col-groups
    const int g = lane >> 2, t = lane & 3;
    const int r0 = blockIdx.x * TILE;
    const int imgbase = EDGE ? 0 : 2;

    // ---- gather: 2 rows (g, g+8 of atom ra) x 32 cols per thread,
    //      written straight into fragment-major layout ----
    {
        const int pr = tid >> 2, q = tid & 3;
        const int ra_g = pr >> 3, g_g = pr & 7;
        const int lrA = ra_g * 16 + g_g;
        const int rowA = r0 + lrA, rowB = rowA + 8;
        const bool vA = rowA < count, vB = rowB < count;

        const float *pxA = nullptr, *peA = nullptr, *pxB = nullptr, *peB = nullptr;
        float oe = 0.f;
        if (EDGE) {
            if (vA) { pxA = x + (size_t)__ldg(&src[rowA]) * D; peA = ea + (size_t)rowA * D; }
            if (vB) { pxB = x + (size_t)__ldg(&src[rowB]) * D; peB = ea + (size_t)rowB * D; }
        } else {
            oe = 1.0f + eps[0];
            if (vA) { pxA = x + (size_t)rowA * D; peA = g_agg + (size_t)rowA * D; }
            if (vB) { pxB = x + (size_t)rowB * D; peB = g_agg + (size_t)rowB * D; }
        }

        #pragma unroll
        for (int sl = 0; sl < 4; ++sl) {
            int s = sl * 4 + q;
            float a8[8], b8[8];
            #pragma unroll
            for (int i = 0; i < 8; ++i) { a8[i] = 0.f; b8[i] = 0.f; }
            if (vA) {
                float4 x0 = __ldg((const float4*)(pxA + s * 8));
                float4 x1 = __ldg((const float4*)(pxA + s * 8 + 4));
                float4 e0 = __ldg((const float4*)(peA + s * 8));
                float4 e1 = __ldg((const float4*)(peA + s * 8 + 4));
                if (EDGE) {
                    a8[0] = x0.x + e0.x; a8[1] = x0.y + e0.y; a8[2] = x0.z + e0.z; a8[3] = x0.w + e0.w;
                    a8[4] = x1.x + e1.x; a8[5] = x1.y + e1.y; a8[6] = x1.z + e1.z; a8[7] = x1.w + e1.w;
                } else {
                    a8[0] = fmaf(oe, x0.x, e0.x); a8[1] = fmaf(oe, x0.y, e0.y);
                    a8[2] = fmaf(oe, x0.z, e0.z); a8[3] = fmaf(oe, x0.w, e0.w);
                    a8[4] = fmaf(oe, x1.x, e1.x); a8[5] = fmaf(oe, x1.y, e1.y);
                    a8[6] = fmaf(oe, x1.z, e1.z); a8[7] = fmaf(oe, x1.w, e1.w);
                }
            }
            if (vB) {
                float4 x0 = __ldg((const float4*)(pxB + s * 8));
                float4 x1 = __ldg((const float4*)(pxB + s * 8 + 4));
                float4 e0 = __ldg((const float4*)(peB + s * 8));
                float4 e1 = __ldg((const float4*)(peB + s * 8 + 4));
                if (EDGE) {
                    b8[0] = x0.x + e0.x; b8[1] = x0.y + e0.y; b8[2] = x0.z + e0.z; b8[3] = x0.w + e0.w;
                    b8[4] = x1.x + e1.x; b8[5] = x1.y + e1.y; b8[6] = x1.z + e1.z; b8[7] = x1.w + e1.w;
                } else {
                    b8[0] = fmaf(oe, x0.x, e0.x); b8[1] = fmaf(oe, x0.y, e0.y);
                    b8[2] = fmaf(oe, x0.z, e0.z); b8[3] = fmaf(oe, x0.w, e0.w);
                    b8[4] = fmaf(oe, x1.x, e1.x); b8[5] = fmaf(oe, x1.y, e1.y);
                    b8[6] = fmaf(oe, x1.z, e1.z); b8[7] = fmaf(oe, x1.w, e1.w);
                }
            }
            uint32_t base = (uint32_t)(ra_g * 16 + s) * 33 + g_g * 4;
            #pragma unroll
            for (int tt = 0; tt < 4; ++tt)
                As4[base + tt] = make_uint4(f2tf(a8[tt]), f2tf(b8[tt]),
                                            f2tf(a8[tt + 4]), f2tf(b8[tt + 4]));
        }
    }
    __syncthreads();

    const uint4* Bq1 = (const uint4*)&g_Bfrag[imgbase][0]     + wn * 2048 + lane;
    const uint4* Bq2 = (const uint4*)&g_Bfrag[imgbase + 1][0] + wn * 2048 + lane;
    const int ra0 = wm * 2;

    float acc[2][8][4];

    // ---- GEMM1 ----
    do_gemm(As4, Bq1, ra0, lane, acc);
    __syncthreads();

    // ---- epilogue1: H = GELU(C + b1) -> fragment-major smem (shfl re-pair) ----
    #pragma unroll
    for (int ca = 0; ca < 8; ++ca) {
        int colb = wn * 64 + ca * 8 + 2 * t;
        float bb0 = __ldg(&b1[colb]), bb1 = __ldg(&b1[colb + 1]);
        int sH = wn * 8 + ca;
        #pragma unroll
        for (int ma = 0; ma < 2; ++ma) {
            float v0 = gelu_exact(acc[ma][ca][0] + bb0);
            float v1 = gelu_exact(acc[ma][ca][1] + bb1);
            float v2 = gelu_exact(acc[ma][ca][2] + bb0);
            float v3 = gelu_exact(acc[ma][ca][3] + bb1);
            float y0 = __shfl_xor_sync(0xffffffffu, (t < 2) ? v1 : v0, 2);
            float y1 = __shfl_xor_sync(0xffffffffu, (t < 2) ? v3 : v2, 2);
            uint4 f;
            int tp;
            if (t < 2) { f = make_uint4(f2tf(v0), f2tf(v2), f2tf(y0), f2tf(y1)); tp = 2 * t; }
            else       { f = make_uint4(f2tf(y0), f2tf(y1), f2tf(v1), f2tf(v3)); tp = 2 * t - 3; }
            As4[((ra0 + ma) * 16 + sH) * 33 + g * 4 + tp] = f;
        }
    }
    __syncthreads();

    // ---- GEMM2 ----
    do_gemm(As4, Bq2, ra0, lane, acc);
    __syncthreads();

    // ---- epilogue2: raw C2 -> linear smem (fp32) ----
    #pragma unroll
    for (int ca = 0; ca < 8; ++ca) {
        int col = wn * 64 + ca * 8 + 2 * t;
        #pragma unroll
        for (int ma = 0; ma < 2; ++ma) {
            int row = wm * 32 + ma * 16 + g;
            *(float2*)(Asf + row * 132 + col)       = make_float2(acc[ma][ca][0], acc[ma][ca][1]);
            *(float2*)(Asf + (row + 8) * 132 + col) = make_float2(acc[ma][ca][2], acc[ma][ca][3]);
        }
    }
    __syncthreads();

    // ---- output: coalesced + bias; edge -> red.v4 scatter, node -> store ----
    {
        int c4 = lane * 4;
        float4 bias = *(const float4*)&b2[c4];
        int rbase = wid * 16;
        #pragma unroll
        for (int i = 0; i < 16; ++i) {
            int r = rbase + i;
            int row = r0 + r;
            if (row < count) {
                float4 v = *(float4*)(Asf + r * 132 + c4);
                v.x += bias.x; v.y += bias.y; v.z += bias.z; v.w += bias.w;
                if (EDGE) {
                    int dn = __ldg(&dst[row]);
                    red_add_v4(g_agg + (size_t)dn * D + c4, v);
                } else {
                    *(float4*)(out + (size_t)row * D + c4) = v;
                }
            }
        }
    }
}

// ---------------------------------------------------------------------------
// Inputs: x, edge_index(int32 [2,E]), edge_attr, We1, be1, We2, be2,
//         Wu1, bu1, Wu2, bu2, eps
// ---------------------------------------------------------------------------
extern "C" void kernel_launch(void* const* d_in, const int* in_sizes, int n_in,
                              void* d_out, int out_size)
{
    const float* x   = (const float*)d_in[0];
    const int*   ei  = (const int*)d_in[1];
    const float* ea  = (const float*)d_in[2];
    const float* We1 = (const float*)d_in[3];
    const float* be1 = (const float*)d_in[4];
    const float* We2 = (const float*)d_in[5];
    const float* be2 = (const float*)d_in[6];
    const float* Wu1 = (const float*)d_in[7];
    const float* bu1 = (const float*)d_in[8];
    const float* Wu2 = (const float*)d_in[9];
    const float* bu2 = (const float*)d_in[10];
    const float* eps = (const float*)d_in[11];
    float*       out = (float*)d_out;

    const int N = in_sizes[0] / D;
    const int E = in_sizes[1] / 2;
    const int* src = ei;
    const int* dst = ei + E;

    const int SMEM_BYTES = 4224 * 16;   // 67584 — fragment/linear tile => 2 CTAs/SM
    cudaFuncSetAttribute(fused_mlp_mma<true>,  cudaFuncAttributeMaxDynamicSharedMemorySize, SMEM_BYTES);
    cudaFuncSetAttribute(fused_mlp_mma<false>, cudaFuncAttributeMaxDynamicSharedMemorySize, SMEM_BYTES);

    // prep weights + zero g_agg in one kernel (no separate memset launch)
    prep_weights<<<1024, 256>>>(We1, We2, Wu1, Wu2, (size_t)N * D);

    int eblocks = (E + TILE - 1) / TILE;
    fused_mlp_mma<true><<<eblocks, NTHR, SMEM_BYTES>>>(x, src, dst, ea, be1, be2, eps, out, E);

    int nblocks = (N + TILE - 1) / TILE;
    fused_mlp_mma<false><<<nblocks, NTHR, SMEM_BYTES>>>(x, src, dst, ea, bu1, bu2, eps, out, N);
}

// round 8
// speedup vs baseline: 1.9876x; 1.0757x over previous
#include <cuda_runtime.h>
#include <math.h>
#include <stdint.h>

#define D      128
#define TILE   128
#define NTHR   256
#define MAXN   51200

// ---------------------------------------------------------------------------
// Static device scratch (no cudaMalloc allowed)
// ---------------------------------------------------------------------------
__device__ float    g_agg[(size_t)MAXN * D];     // scatter-add target
__device__ uint32_t g_Bfrag[4][16384];           // tf32 W images, uint4-packed frag order
// 0 = We1, 1 = We2, 2 = Wu1, 3 = Wu2

__device__ __forceinline__ uint32_t f2tf(float f) {
    uint32_t r;
    asm("cvt.rna.tf32.f32 %0, %1;" : "=r"(r) : "f"(f));
    return r;
}

__device__ __forceinline__ float gelu_exact(float v) {
    return 0.5f * v * (1.0f + erff(v * 0.70710678118654752f));
}

__device__ __forceinline__ void mma_tf32(float* c,
                                         uint32_t a0, uint32_t a1, uint32_t a2, uint32_t a3,
                                         uint32_t b0, uint32_t b1) {
    asm volatile(
        "mma.sync.aligned.m16n8k8.row.col.f32.tf32.tf32.f32 "
        "{%0,%1,%2,%3}, {%4,%5,%6,%7}, {%8,%9}, {%0,%1,%2,%3};"
        : "+f"(c[0]), "+f"(c[1]), "+f"(c[2]), "+f"(c[3])
        : "r"(a0), "r"(a1), "r"(a2), "r"(a3), "r"(b0), "r"(b1));
}

__device__ __forceinline__ void red_add_v4(float* p, float4 v) {
    asm volatile("red.global.add.v4.f32 [%0], {%1,%2,%3,%4};"
                 :: "l"(p), "f"(v.x), "f"(v.y), "f"(v.z), "f"(v.w) : "memory");
}

// ---------------------------------------------------------------------------
// prep: (a) W[k][n] -> tf32 bits, uint4-packed fragment order:
//   idx32 = ((ca*8 + (s>>1))*32 + lane)*4 + (s&1)*2 + slot
//   ca = n>>3, s = k>>3, lane = ((n&7)<<2)|(k&3), slot = (k>>2)&1
// (b) zero g_agg (grid-stride).
// ---------------------------------------------------------------------------
__global__ void prep_weights(const float* __restrict__ We1, const float* __restrict__ We2,
                             const float* __restrict__ Wu1, const float* __restrict__ Wu2,
                             size_t nd)
{
    int id = blockIdx.x * blockDim.x + threadIdx.x;
    if (id < 4 * 16384) {
        int m = id >> 14, r = id & 16383, k = r >> 7, n = r & 127;
        const float* W = (m == 0) ? We1 : (m == 1) ? We2 : (m == 2) ? Wu1 : Wu2;
        float v = W[k * D + n];
        int ca = n >> 3, s = k >> 3, lane = ((n & 7) << 2) | (k & 3), slot = (k >> 2) & 1;
        int idx = ((ca * 8 + (s >> 1)) * 32 + lane) * 4 + (s & 1) * 2 + slot;
        g_Bfrag[m][idx] = f2tf(v);
    }
    size_t stride = (size_t)gridDim.x * blockDim.x * 4;
    float4 z = make_float4(0.f, 0.f, 0.f, 0.f);
    for (size_t i = (size_t)id * 4; i < nd; i += stride)
        *(float4*)(g_agg + i) = z;
}

// ---------------------------------------------------------------------------
// 64(rows)x32(cols)x128 GEMM slice per warp; A fragment-major smem (LDS.128),
// B uint4 frags from L1-resident global image (LDG.128).
// Bq = image_u4 + wn*1024 + lane; ra0 = wm*4.
// ---------------------------------------------------------------------------
__device__ __forceinline__ void do_gemm(const uint4* __restrict__ As4,
                                        const uint4* __restrict__ Bq,
                                        int ra0, int lane,
                                        float acc[4][4][4])
{
    #pragma unroll
    for (int r = 0; r < 4; ++r)
        #pragma unroll
        for (int ca = 0; ca < 4; ++ca)
            #pragma unroll
            for (int q = 0; q < 4; ++q) acc[r][ca][q] = 0.f;

    #pragma unroll
    for (int sp = 0; sp < 8; ++sp) {
        int s0 = sp * 2, s1 = s0 + 1;
        uint4 a0[4], a1[4];
        #pragma unroll
        for (int r = 0; r < 4; ++r) {
            a0[r] = As4[((ra0 + r) * 16 + s0) * 33 + lane];
            a1[r] = As4[((ra0 + r) * 16 + s1) * 33 + lane];
        }
        #pragma unroll
        for (int ca = 0; ca < 4; ++ca) {
            uint4 b = __ldg(Bq + (ca * 8 + sp) * 32);
            #pragma unroll
            for (int r = 0; r < 4; ++r) {
                mma_tf32(acc[r][ca], a0[r].x, a0[r].y, a0[r].z, a0[r].w, b.x, b.y);
                mma_tf32(acc[r][ca], a1[r].x, a1[r].y, a1[r].z, a1[r].w, b.z, b.w);
            }
        }
    }
}

// ---------------------------------------------------------------------------
// Fused 2-layer MLP on a 128-row tile. 8 warps: 2 row-groups x 4 col-groups.
// smem = one 67.6KB fragment/linear tile buffer -> 2 CTAs/SM.
// ---------------------------------------------------------------------------
template <bool EDGE>
__global__ void __launch_bounds__(NTHR, 2) fused_mlp_mma(
    const float* __restrict__ x,
    const int*   __restrict__ src,
    const int*   __restrict__ dst,
    const float* __restrict__ ea,
    const float* __restrict__ b1,
    const float* __restrict__ b2,
    const float* __restrict__ eps,
    float*       __restrict__ out,
    int count)
{
    extern __shared__ float Asf[];                 // 16896 floats = 4224 uint4
    uint4* As4 = (uint4*)Asf;

    const int tid  = threadIdx.x;
    const int lane = tid & 31, wid = tid >> 5;
    const int wm = wid & 1, wn = wid >> 1;         // 2 row-groups x 4 col-groups
    const int g = lane >> 2, t = lane & 3;
    const int r0 = blockIdx.x * TILE;
    const int imgbase = EDGE ? 0 : 2;

    // ---- gather: 2 rows (g, g+8 of atom ra) x 32 cols per thread,
    //      written straight into fragment-major layout ----
    {
        const int pr = tid >> 2, q = tid & 3;
        const int ra_g = pr >> 3, g_g = pr & 7;
        const int lrA = ra_g * 16 + g_g;
        const int rowA = r0 + lrA, rowB = rowA + 8;
        const bool vA = rowA < count, vB = rowB < count;

        const float *pxA = nullptr, *peA = nullptr, *pxB = nullptr, *peB = nullptr;
        float oe = 0.f;
        if (EDGE) {
            if (vA) { pxA = x + (size_t)__ldg(&src[rowA]) * D; peA = ea + (size_t)rowA * D; }
            if (vB) { pxB = x + (size_t)__ldg(&src[rowB]) * D; peB = ea + (size_t)rowB * D; }
        } else {
            oe = 1.0f + eps[0];
            if (vA) { pxA = x + (size_t)rowA * D; peA = g_agg + (size_t)rowA * D; }
            if (vB) { pxB = x + (size_t)rowB * D; peB = g_agg + (size_t)rowB * D; }
        }

        #pragma unroll
        for (int sl = 0; sl < 4; ++sl) {
            int s = sl * 4 + q;
            float a8[8], b8[8];
            #pragma unroll
            for (int i = 0; i < 8; ++i) { a8[i] = 0.f; b8[i] = 0.f; }
            if (vA) {
                float4 x0 = __ldg((const float4*)(pxA + s * 8));
                float4 x1 = __ldg((const float4*)(pxA + s * 8 + 4));
                float4 e0 = __ldg((const float4*)(peA + s * 8));
                float4 e1 = __ldg((const float4*)(peA + s * 8 + 4));
                if (EDGE) {
                    a8[0] = x0.x + e0.x; a8[1] = x0.y + e0.y; a8[2] = x0.z + e0.z; a8[3] = x0.w + e0.w;
                    a8[4] = x1.x + e1.x; a8[5] = x1.y + e1.y; a8[6] = x1.z + e1.z; a8[7] = x1.w + e1.w;
                } else {
                    a8[0] = fmaf(oe, x0.x, e0.x); a8[1] = fmaf(oe, x0.y, e0.y);
                    a8[2] = fmaf(oe, x0.z, e0.z); a8[3] = fmaf(oe, x0.w, e0.w);
                    a8[4] = fmaf(oe, x1.x, e1.x); a8[5] = fmaf(oe, x1.y, e1.y);
                    a8[6] = fmaf(oe, x1.z, e1.z); a8[7] = fmaf(oe, x1.w, e1.w);
                }
            }
            if (vB) {
                float4 x0 = __ldg((const float4*)(pxB + s * 8));
                float4 x1 = __ldg((const float4*)(pxB + s * 8 + 4));
                float4 e0 = __ldg((const float4*)(peB + s * 8));
                float4 e1 = __ldg((const float4*)(peB + s * 8 + 4));
                if (EDGE) {
                    b8[0] = x0.x + e0.x; b8[1] = x0.y + e0.y; b8[2] = x0.z + e0.z; b8[3] = x0.w + e0.w;
                    b8[4] = x1.x + e1.x; b8[5] = x1.y + e1.y; b8[6] = x1.z + e1.z; b8[7] = x1.w + e1.w;
                } else {
                    b8[0] = fmaf(oe, x0.x, e0.x); b8[1] = fmaf(oe, x0.y, e0.y);
                    b8[2] = fmaf(oe, x0.z, e0.z); b8[3] = fmaf(oe, x0.w, e0.w);
                    b8[4] = fmaf(oe, x1.x, e1.x); b8[5] = fmaf(oe, x1.y, e1.y);
                    b8[6] = fmaf(oe, x1.z, e1.z); b8[7] = fmaf(oe, x1.w, e1.w);
                }
            }
            uint32_t base = (uint32_t)(ra_g * 16 + s) * 33 + g_g * 4;
            #pragma unroll
            for (int tt = 0; tt < 4; ++tt)
                As4[base + tt] = make_uint4(f2tf(a8[tt]), f2tf(b8[tt]),
                                            f2tf(a8[tt + 4]), f2tf(b8[tt + 4]));
        }
    }
    __syncthreads();

    const uint4* Bq1 = (const uint4*)&g_Bfrag[imgbase][0]     + wn * 1024 + lane;
    const uint4* Bq2 = (const uint4*)&g_Bfrag[imgbase + 1][0] + wn * 1024 + lane;
    const int ra0 = wm * 4;

    float acc[4][4][4];

    // ---- GEMM1 ----
    do_gemm(As4, Bq1, ra0, lane, acc);
    __syncthreads();

    // ---- epilogue1: H = GELU(C + b1) -> fragment-major smem (shfl re-pair) ----
    #pragma unroll
    for (int ca = 0; ca < 4; ++ca) {
        int colb = wn * 32 + ca * 8 + 2 * t;
        float bb0 = __ldg(&b1[colb]), bb1 = __ldg(&b1[colb + 1]);
        int sH = wn * 4 + ca;
        #pragma unroll
        for (int ma = 0; ma < 4; ++ma) {
            float v0 = gelu_exact(acc[ma][ca][0] + bb0);
            float v1 = gelu_exact(acc[ma][ca][1] + bb1);
            float v2 = gelu_exact(acc[ma][ca][2] + bb0);
            float v3 = gelu_exact(acc[ma][ca][3] + bb1);
            float y0 = __shfl_xor_sync(0xffffffffu, (t < 2) ? v1 : v0, 2);
            float y1 = __shfl_xor_sync(0xffffffffu, (t < 2) ? v3 : v2, 2);
            uint4 f;
            int tp;
            if (t < 2) { f = make_uint4(f2tf(v0), f2tf(v2), f2tf(y0), f2tf(y1)); tp = 2 * t; }
            else       { f = make_uint4(f2tf(y0), f2tf(y1), f2tf(v1), f2tf(v3)); tp = 2 * t - 3; }
            As4[((ra0 + ma) * 16 + sH) * 33 + g * 4 + tp] = f;
        }
    }
    __syncthreads();

    // ---- GEMM2 ----
    do_gemm(As4, Bq2, ra0, lane, acc);
    __syncthreads();

    // ---- epilogue2: raw C2 -> linear smem (fp32) ----
    #pragma unroll
    for (int ca = 0; ca < 4; ++ca) {
        int col = wn * 32 + ca * 8 + 2 * t;
        #pragma unroll
        for (int ma = 0; ma < 4; ++ma) {
            int row = wm * 64 + ma * 16 + g;
            *(float2*)(Asf + row * 132 + col)       = make_float2(acc[ma][ca][0], acc[ma][ca][1]);
            *(float2*)(Asf + (row + 8) * 132 + col) = make_float2(acc[ma][ca][2], acc[ma][ca][3]);
        }
    }
    __syncthreads();

    // ---- output: coalesced + bias; edge -> red.v4 scatter, node -> store ----
    {
        int c4 = lane * 4;
        float4 bias = *(const float4*)&b2[c4];
        int rbase = wid * 16;
        #pragma unroll
        for (int i = 0; i < 16; ++i) {
            int r = rbase + i;
            int row = r0 + r;
            if (row < count) {
                float4 v = *(float4*)(Asf + r * 132 + c4);
                v.x += bias.x; v.y += bias.y; v.z += bias.z; v.w += bias.w;
                if (EDGE) {
                    int dn = __ldg(&dst[row]);
                    red_add_v4(g_agg + (size_t)dn * D + c4, v);
                } else {
                    *(float4*)(out + (size_t)row * D + c4) = v;
                }
            }
        }
    }
}

// ---------------------------------------------------------------------------
// Inputs: x, edge_index(int32 [2,E]), edge_attr, We1, be1, We2, be2,
//         Wu1, bu1, Wu2, bu2, eps
// ---------------------------------------------------------------------------
extern "C" void kernel_launch(void* const* d_in, const int* in_sizes, int n_in,
                              void* d_out, int out_size)
{
    const float* x   = (const float*)d_in[0];
    const int*   ei  = (const int*)d_in[1];
    const float* ea  = (const float*)d_in[2];
    const float* We1 = (const float*)d_in[3];
    const float* be1 = (const float*)d_in[4];
    const float* We2 = (const float*)d_in[5];
    const float* be2 = (const float*)d_in[6];
    const float* Wu1 = (const float*)d_in[7];
    const float* bu1 = (const float*)d_in[8];
    const float* Wu2 = (const float*)d_in[9];
    const float* bu2 = (const float*)d_in[10];
    const float* eps = (const float*)d_in[11];
    float*       out = (float*)d_out;

    const int N = in_sizes[0] / D;
    const int E = in_sizes[1] / 2;
    const int* src = ei;
    const int* dst = ei + E;

    const int SMEM_BYTES = 4224 * 16;   // 67584 — fragment/linear tile => 2 CTAs/SM
    cudaFuncSetAttribute(fused_mlp_mma<true>,  cudaFuncAttributeMaxDynamicSharedMemorySize, SMEM_BYTES);
    cudaFuncSetAttribute(fused_mlp_mma<false>, cudaFuncAttributeMaxDynamicSharedMemorySize, SMEM_BYTES);

    prep_weights<<<1024, 256>>>(We1, We2, Wu1, Wu2, (size_t)N * D);

    int eblocks = (E + TILE - 1) / TILE;
    fused_mlp_mma<true><<<eblocks, NTHR, SMEM_BYTES>>>(x, src, dst, ea, be1, be2, eps, out, E);

    int nblocks = (N + TILE - 1) / TILE;
    fused_mlp_mma<false><<<nblocks, NTHR, SMEM_BYTES>>>(x, src, dst, ea, bu1, bu2, eps, out, N);
}